// round 14
// baseline (speedup 1.0000x reference)
#include <cuda_runtime.h>
#include <cuda_bf16.h>
#include <cuda_fp16.h>
#include <cstdint>
#include <math.h>

#define NN 100000
#define NE 1600000
#define HF 128
#define NG 64
#define NC 10
#define SCAN_B 1024
#define NB_SCAN ((NN + SCAN_B - 1) / SCAN_B)   // 98
#define POOL_CH 256

// GEMM smem tile geometry: 128 rows x 128 fp16, padded stride 136 elems (272B)
#define TSTR 136
#define TILE_BYTES (128 * TSTR * 2)            // 34816
#define OFF_A   0
#define OFF_BHI (TILE_BYTES)
#define OFF_BLO (2 * TILE_BYTES)
#define SMB     (3 * TILE_BYTES)               // 104448 -> 2 CTA/SM

// ---------------- scratch (static device globals; no allocation) ----------------
__device__ __half g_h  [NN * HF];             // GEMM output per layer (fp16 rows, 256B)
__device__ __half g_ax [NN * HF];             // activation (GEMM A input, fp16)
__device__ __half g_whi[4 * HF * HF];         // W^T hi per layer, layout [l][n][k]
__device__ __half g_wlo[4 * HF * HF];         // W^T lo per layer
__device__ float g_xB [NN * HF];              // final layer fp32 output (for pooling)
__device__ int   g_deg   [NN];
__device__ float g_dinv  [NN];
__device__ float g_invdeg[NN];
__device__ int   g_rowptr[NN + 1];
__device__ int   g_cursor[NN];
__device__ uint2 g_edge  [NE];                // packed {src, norm_bits}
__device__ int   g_bsums [128];
__device__ float g_gmax  [NG * HF];
__device__ float g_gsum  [NG * HF];
__device__ int   g_gcnt  [NG];

// ================= mma.sync / ldmatrix helpers (arch-portable PTX) =================
__device__ __forceinline__ uint32_t smem_u32(const void* p) {
    uint32_t a;
    asm("{ .reg .u64 t; cvta.to.shared.u64 t, %1; cvt.u32.u64 %0, t; }" : "=r"(a) : "l"(p));
    return a;
}
__device__ __forceinline__ void ldsm_x4(uint32_t* r, uint32_t addr) {
    asm volatile("ldmatrix.sync.aligned.m8n8.x4.shared.b16 {%0,%1,%2,%3}, [%4];"
        : "=r"(r[0]), "=r"(r[1]), "=r"(r[2]), "=r"(r[3]) : "r"(addr));
}
__device__ __forceinline__ void ldsm_x2(uint32_t* r, uint32_t addr) {
    asm volatile("ldmatrix.sync.aligned.m8n8.x2.shared.b16 {%0,%1}, [%2];"
        : "=r"(r[0]), "=r"(r[1]) : "r"(addr));
}
__device__ __forceinline__ void mma_f16(float* c, const uint32_t* a, const uint32_t* b) {
    asm volatile("mma.sync.aligned.m16n8k16.row.col.f32.f16.f16.f32 "
        "{%0,%1,%2,%3}, {%4,%5,%6,%7}, {%8,%9}, {%0,%1,%2,%3};"
        : "+f"(c[0]), "+f"(c[1]), "+f"(c[2]), "+f"(c[3])
        : "r"(a[0]), "r"(a[1]), "r"(a[2]), "r"(a[3]), "r"(b[0]), "r"(b[1]));
}

// ---------------- degree / normalization ----------------
__global__ void k_deg_init() {
    int i = blockIdx.x * blockDim.x + threadIdx.x;
    if (i < NN) g_deg[i] = 1;
}
__global__ void k_deg_count(const int* __restrict__ dst) {
    int e = blockIdx.x * blockDim.x + threadIdx.x;
    if (e < NE) atomicAdd(&g_deg[dst[e]], 1);
}
__global__ void k_dinv() {
    int i = blockIdx.x * blockDim.x + threadIdx.x;
    if (i < NN) {
        float d = (float)g_deg[i];
        g_dinv[i]   = rsqrtf(d);
        g_invdeg[i] = 1.0f / d;
    }
}

// ---------------- exclusive scan of in-degree -> row_ptr ----------------
__global__ void k_scan1() {
    __shared__ int sm[SCAN_B];
    int tid = threadIdx.x;
    int i = blockIdx.x * SCAN_B + tid;
    int v = (i < NN) ? (g_deg[i] - 1) : 0;
    sm[tid] = v;
    __syncthreads();
    for (int off = 1; off < SCAN_B; off <<= 1) {
        int t = (tid >= off) ? sm[tid - off] : 0;
        __syncthreads();
        sm[tid] += t;
        __syncthreads();
    }
    if (i < NN) g_rowptr[i] = sm[tid] - v;
    if (tid == SCAN_B - 1) g_bsums[blockIdx.x] = sm[tid];
}
__global__ void k_scan2() {
    __shared__ int sm[128];
    int tid = threadIdx.x;
    int v = (tid < NB_SCAN) ? g_bsums[tid] : 0;
    sm[tid] = v;
    __syncthreads();
    for (int off = 1; off < 128; off <<= 1) {
        int t = (tid >= off) ? sm[tid - off] : 0;
        __syncthreads();
        sm[tid] += t;
        __syncthreads();
    }
    if (tid < NB_SCAN) g_bsums[tid] = sm[tid] - v;
}
__global__ void k_scan3() {
    int i = blockIdx.x * blockDim.x + threadIdx.x;
    if (i < NN) {
        int r = g_rowptr[i] + g_bsums[i / SCAN_B];
        g_rowptr[i] = r;
        g_cursor[i] = r;
    }
    if (i == 0) g_rowptr[NN] = NE;
}
__global__ void k_edge_scatter(const int* __restrict__ src, const int* __restrict__ dst) {
    int e = blockIdx.x * blockDim.x + threadIdx.x;
    if (e < NE) {
        int s = src[e];
        int d = dst[e];
        int pos = atomicAdd(&g_cursor[d], 1);
        float norm = g_dinv[s] * g_dinv[d];
        g_edge[pos] = make_uint2((unsigned)s, __float_as_uint(norm));
    }
}

// ---------------- x -> fp16 A ----------------
__global__ void k_split_x(const float* __restrict__ x) {
    int i = blockIdx.x * blockDim.x + threadIdx.x;   // handles 4 floats
    if (i >= NN * HF / 4) return;
    float4 v = ((const float4*)x)[i];
    __half2 a = __floats2half2_rn(v.x, v.y);
    __half2 b = __floats2half2_rn(v.z, v.w);
    ((uint2*)g_ax)[i] = make_uint2(*(uint32_t*)&a, *(uint32_t*)&b);
}

// ---------------- W^T fp16 hi/lo split (all 4 layers) ----------------
__global__ void k_wsplit(const float* __restrict__ W0, const float* __restrict__ W1,
                         const float* __restrict__ W2, const float* __restrict__ W3) {
    int i = blockIdx.x * blockDim.x + threadIdx.x;
    if (i >= 4 * HF * HF) return;
    int l = i >> 14;
    int rem = i & 16383;
    int n = rem >> 7;        // output col
    int k = rem & 127;       // input dim
    const float* W = (l == 0) ? W0 : (l == 1) ? W1 : (l == 2) ? W2 : W3;
    float v = W[k * HF + n];
    __half h = __float2half_rn(v);
    __half lo = __float2half_rn(v - __half2float(h));
    g_whi[i] = h;    // layout: [l][n][k]  (= col-major B for mma row.col)
    g_wlo[i] = lo;
}

// ---------------- HMMA fp16x2 GEMM: g_h = A @ (Whi + Wlo) ----------------
// 128x128x128 per CTA (2 CTA/SM), 256 threads = 8 warps (2x4), warp tile 64x32.
__device__ __forceinline__ void fill_tile(char* smem, int off,
                                          const void* __restrict__ g,
                                          int row0, bool clampA, int tid) {
    const uint4* src = (const uint4*)g;
#pragma unroll
    for (int it = 0; it < 8; it++) {
        int idx = it * 256 + tid;       // 0..2047 (128 rows x 16 uint4)
        int row = idx >> 4;
        int seg = idx & 15;
        int grow = clampA ? min(row0 + row, NN - 1) : row;
        uint4 v = src[grow * 16 + seg];
        *(uint4*)(smem + off + row * (TSTR * 2) + seg * 16) = v;
    }
}

__global__ __launch_bounds__(256) void k_hgemm(int l) {
    extern __shared__ char smem[];
    const int tid  = threadIdx.x;
    const int warp = tid >> 5;
    const int lane = tid & 31;
    const int wm = warp >> 2;           // 0..1  (m block of 64)
    const int wn = warp & 3;            // 0..3  (n block of 32)
    const int row0 = blockIdx.x * 128;

    fill_tile(smem, OFF_A,   g_ax,              row0, true,  tid);
    fill_tile(smem, OFF_BHI, g_whi + l * HF * HF, 0,  false, tid);
    fill_tile(smem, OFF_BLO, g_wlo + l * HF * HF, 0,  false, tid);
    __syncthreads();

    const uint32_t sbase = smem_u32(smem);

    const int lgrp  = lane >> 3;        // 0..3
    const int lrow  = lane & 7;         // 0..7
    const int a_r   = (lgrp & 1) * 8 + lrow;
    const int a_k   = (lgrp >> 1) * 8;
    const int b_r   = lrow;
    const int b_k   = (lgrp & 1) * 8;

    float acc[4][4][4];
#pragma unroll
    for (int i = 0; i < 4; i++)
#pragma unroll
        for (int j = 0; j < 4; j++)
#pragma unroll
            for (int q = 0; q < 4; q++) acc[i][j][q] = 0.0f;

#pragma unroll
    for (int kc = 0; kc < 8; kc++) {
        uint32_t af[4][4], bhi[4][2], blo[4][2];
#pragma unroll
        for (int mf = 0; mf < 4; mf++) {
            int mrow = wm * 64 + mf * 16 + a_r;
            uint32_t byteoff = (uint32_t)(mrow * (TSTR * 2) + (kc * 16 + a_k) * 2);
            ldsm_x4(af[mf], sbase + OFF_A + byteoff);
        }
#pragma unroll
        for (int nf = 0; nf < 4; nf++) {
            int nrow = wn * 32 + nf * 8 + b_r;
            uint32_t byteoff = (uint32_t)(nrow * (TSTR * 2) + (kc * 16 + b_k) * 2);
            ldsm_x2(bhi[nf], sbase + OFF_BHI + byteoff);
            ldsm_x2(blo[nf], sbase + OFF_BLO + byteoff);
        }
#pragma unroll
        for (int mf = 0; mf < 4; mf++)
#pragma unroll
            for (int nf = 0; nf < 4; nf++) {
                mma_f16(acc[mf][nf], af[mf], bhi[nf]);
                mma_f16(acc[mf][nf], af[mf], blo[nf]);
            }
    }

    // epilogue: c frag lane l -> rows l/4 and l/4+8, cols (l%4)*2; store fp16 pairs
    const int crow = lane >> 2;
    const int ccol = (lane & 3) * 2;
#pragma unroll
    for (int mf = 0; mf < 4; mf++) {
        int r0 = row0 + wm * 64 + mf * 16 + crow;
        int r1 = r0 + 8;
#pragma unroll
        for (int nf = 0; nf < 4; nf++) {
            int c = wn * 32 + nf * 8 + ccol;
            if (r0 < NN)
                *(__half2*)&g_h[r0 * HF + c] = __floats2half2_rn(acc[mf][nf][0], acc[mf][nf][1]);
            if (r1 < NN)
                *(__half2*)&g_h[r1 * HF + c] = __floats2half2_rn(acc[mf][nf][2], acc[mf][nf][3]);
        }
    }
}

// ---------------- CSR gather aggregation + self-loop + bias + tanh ----------------
// one warp per node, lane owns 4 features (uint2 = 4 fp16).
// Software-pipelined: edge metadata register double-buffered one group ahead, so
// next-meta loads and current gathers issue together (breaks meta->gather chain).
__device__ __forceinline__ float4 h4_from_u2(uint2 u) {
    __half2 p0 = *(__half2*)&u.x;
    __half2 p1 = *(__half2*)&u.y;
    float2 f0 = __half22float2(p0);
    float2 f1 = __half22float2(p1);
    return make_float4(f0.x, f0.y, f1.x, f1.y);
}
__device__ __forceinline__ void acc4(float4& acc, uint2 hu, float w) {
    float4 v = h4_from_u2(hu);
    acc.x += w * v.x; acc.y += w * v.y; acc.z += w * v.z; acc.w += w * v.w;
}

__global__ __launch_bounds__(256) void k_agg(const float* __restrict__ bias, int last) {
    int node = blockIdx.x * 8 + (threadIdx.x >> 5);
    if (node >= NN) return;
    int lane = threadIdx.x & 31;
    const uint2* __restrict__ h2 = (const uint2*)g_h;   // row = 32 uint2

    int beg = g_rowptr[node];
    int end = g_rowptr[node + 1];

    float4 acc = make_float4(0.f, 0.f, 0.f, 0.f);
    int e = beg;

    if (e + 3 < end) {
        // prologue: load first meta group
        uint2 m0 = g_edge[e], m1 = g_edge[e + 1], m2 = g_edge[e + 2], m3 = g_edge[e + 3];
        e += 4;
        // steady state: prefetch next meta group, gather current
        for (; e + 3 < end; e += 4) {
            uint2 n0 = g_edge[e],     n1 = g_edge[e + 1];
            uint2 n2 = g_edge[e + 2], n3 = g_edge[e + 3];
            uint2 v0 = h2[m0.x * 32 + lane];
            uint2 v1 = h2[m1.x * 32 + lane];
            uint2 v2 = h2[m2.x * 32 + lane];
            uint2 v3 = h2[m3.x * 32 + lane];
            acc4(acc, v0, __uint_as_float(m0.y));
            acc4(acc, v1, __uint_as_float(m1.y));
            acc4(acc, v2, __uint_as_float(m2.y));
            acc4(acc, v3, __uint_as_float(m3.y));
            m0 = n0; m1 = n1; m2 = n2; m3 = n3;
        }
        // drain the last prefetched group
        uint2 v0 = h2[m0.x * 32 + lane];
        uint2 v1 = h2[m1.x * 32 + lane];
        uint2 v2 = h2[m2.x * 32 + lane];
        uint2 v3 = h2[m3.x * 32 + lane];
        acc4(acc, v0, __uint_as_float(m0.y));
        acc4(acc, v1, __uint_as_float(m1.y));
        acc4(acc, v2, __uint_as_float(m2.y));
        acc4(acc, v3, __uint_as_float(m3.y));
    }
    for (; e < end; e++) {
        uint2 m = g_edge[e];
        acc4(acc, h2[m.x * 32 + lane], __uint_as_float(m.y));
    }

    float4 hs = h4_from_u2(h2[node * 32 + lane]);
    float inv = g_invdeg[node];
    float4 bb = ((const float4*)bias)[lane];
    float4 o;
    o.x = tanhf(acc.x + inv * hs.x + bb.x);
    o.y = tanhf(acc.y + inv * hs.y + bb.y);
    o.z = tanhf(acc.z + inv * hs.z + bb.z);
    o.w = tanhf(acc.w + inv * hs.w + bb.w);

    if (last) {
        ((float4*)g_xB)[node * 32 + lane] = o;
    } else {
        __half2 a = __floats2half2_rn(o.x, o.y);
        __half2 b = __floats2half2_rn(o.z, o.w);
        ((uint2*)g_ax)[node * 32 + lane] = make_uint2(*(uint32_t*)&a, *(uint32_t*)&b);
    }
}

// ---------------- pooling ----------------
__global__ void k_pool_init() {
    int i = blockIdx.x * blockDim.x + threadIdx.x;
    if (i < NG * HF) {
        g_gmax[i] = -INFINITY;
        g_gsum[i] = 0.0f;
    }
    if (i < NG) g_gcnt[i] = 0;
}

__device__ __forceinline__ void atomicMaxF(float* addr, float v) {
    if (v >= 0.0f) atomicMax((int*)addr, __float_as_int(v));
    else           atomicMin((unsigned int*)addr, __float_as_uint(v));
}

__global__ __launch_bounds__(128) void k_pool(const int* __restrict__ batch) {
    const float* __restrict__ x = g_xB;
    int t  = threadIdx.x;
    int n0 = blockIdx.x * POOL_CH;
    if (n0 >= NN) return;
    int n1 = min(n0 + POOL_CH, NN);

    int cur = -1;
    float rmax = -INFINITY, rsum = 0.0f;
    int rcnt = 0;
    for (int n = n0; n < n1; n++) {
        int g = batch[n];
        if (g != cur) {
            if (cur >= 0) {
                atomicMaxF(&g_gmax[cur * HF + t], rmax);
                atomicAdd(&g_gsum[cur * HF + t], rsum);
                if (t == 0) atomicAdd(&g_gcnt[cur], rcnt);
            }
            cur = g; rmax = -INFINITY; rsum = 0.0f; rcnt = 0;
        }
        float v = x[n * HF + t];
        rmax = fmaxf(rmax, v);
        rsum += v;
        rcnt++;
    }
    if (cur >= 0) {
        atomicMaxF(&g_gmax[cur * HF + t], rmax);
        atomicAdd(&g_gsum[cur * HF + t], rsum);
        if (t == 0) atomicAdd(&g_gcnt[cur], rcnt);
    }
}

// ---------------- finalize ----------------
__global__ __launch_bounds__(256) void k_finalize(const float* __restrict__ Wout,
                                                  const float* __restrict__ bout,
                                                  float* __restrict__ dout, int out_size) {
    __shared__ float p[2 * HF];
    int g = blockIdx.x;
    int t = threadIdx.x;

    float val;
    if (t < HF) {
        val = g_gmax[g * HF + t];
    } else {
        float c = fmaxf((float)g_gcnt[g], 1.0f);
        val = g_gsum[g * HF + (t - HF)] / c;
    }
    p[t] = val;
    int pidx = NG * NC + g * (2 * HF) + t;
    if (pidx < out_size) dout[pidx] = val;
    __syncthreads();

    if (t < NC) {
        float s = bout[t];
#pragma unroll 8
        for (int j = 0; j < 2 * HF; j++) s += p[j] * Wout[j * NC + t];
        int oidx = g * NC + t;
        if (oidx < out_size) dout[oidx] = s;
    }
}

// ---------------- launch ----------------
extern "C" void kernel_launch(void* const* d_in, const int* in_sizes, int n_in,
                              void* d_out, int out_size) {
    const float* x     = (const float*)d_in[0];
    const int*   ei    = (const int*)  d_in[1];
    const int*   batch = (const int*)  d_in[2];
    const float* W0 = (const float*)d_in[3];  const float* b0 = (const float*)d_in[4];
    const float* W1 = (const float*)d_in[5];  const float* b1 = (const float*)d_in[6];
    const float* W2 = (const float*)d_in[7];  const float* b2 = (const float*)d_in[8];
    const float* W3 = (const float*)d_in[9];  const float* b3 = (const float*)d_in[10];
    const float* Wout = (const float*)d_in[11];
    const float* bout = (const float*)d_in[12];
    float* dout = (float*)d_out;

    const int* src = ei;
    const int* dst = ei + NE;

    const int TB = 256;
    const int gN = (NN + TB - 1) / TB;
    const int gE = (NE + TB - 1) / TB;
    const int gGemm = (NN + 127) / 128;       // 782
    const int gAgg  = (NN + 7) / 8;
    const int gPool = (NN + POOL_CH - 1) / POOL_CH;

    // Idempotent, capture-safe (not a stream op).
    cudaFuncSetAttribute(k_hgemm, cudaFuncAttributeMaxDynamicSharedMemorySize, SMB);

    // ---- graph preprocessing ----
    k_deg_init<<<gN, TB>>>();
    k_deg_count<<<gE, TB>>>(dst);
    k_dinv<<<gN, TB>>>();
    k_scan1<<<NB_SCAN, SCAN_B>>>();
    k_scan2<<<1, 128>>>();
    k_scan3<<<gN, TB>>>();
    k_edge_scatter<<<gE, TB>>>(src, dst);

    // ---- precision prep ----
    k_split_x<<<(NN * HF / 4 + TB - 1) / TB, TB>>>(x);
    k_wsplit<<<(4 * HF * HF + TB - 1) / TB, TB>>>(W0, W1, W2, W3);

    // ---- 4 GCN layers ----
    const float* biases[4] = {b0, b1, b2, b3};
    for (int l = 0; l < 4; l++) {
        k_hgemm<<<gGemm, 256, SMB>>>(l);
        k_agg<<<gAgg, 256>>>(biases[l], l == 3 ? 1 : 0);
    }

    // ---- pooling + head ----
    k_pool_init<<<(NG * HF + TB - 1) / TB, TB>>>();
    k_pool<<<gPool, 128>>>(batch);
    k_finalize<<<NG, 256>>>(Wout, bout, dout, out_size);
}

// round 15
// speedup vs baseline: 1.1084x; 1.1084x over previous
#include <cuda_runtime.h>
#include <cuda_bf16.h>
#include <cuda_fp16.h>
#include <cstdint>
#include <math.h>

#define NN 100000
#define NE 1600000
#define HF 128
#define NG 64
#define NC 10
#define SCAN_B 1024
#define NB_SCAN ((NN + SCAN_B - 1) / SCAN_B)   // 98
#define POOL_CH 256

// GEMM smem tile geometry: 128 rows x 128 fp16, padded stride 136 elems (272B)
#define TSTR 136
#define TILE_BYTES (128 * TSTR * 2)            // 34816
#define OFF_A  0
#define OFF_B  (TILE_BYTES)
#define SMB    (2 * TILE_BYTES)                // 69632 -> 2 CTA/SM

// ---------------- scratch (static device globals; no allocation) ----------------
__device__ __half g_h  [NN * HF];             // GEMM output per layer (fp16 rows, 256B)
__device__ __half g_ax [NN * HF];             // activation (GEMM A input, fp16)
__device__ __half g_whi[4 * HF * HF];         // W^T fp16 per layer, layout [l][n][k]
__device__ float g_xB [NN * HF];              // final layer fp32 output (for pooling)
__device__ int   g_deg   [NN];
__device__ float g_dinv  [NN];
__device__ float g_invdeg[NN];
__device__ int   g_rowptr[NN + 1];
__device__ int   g_cursor[NN];
__device__ uint2 g_edge  [NE];                // packed {src, norm_bits}
__device__ int   g_bsums [128];
__device__ float g_gmax  [NG * HF];
__device__ float g_gsum  [NG * HF];
__device__ int   g_gcnt  [NG];

// ================= mma.sync / ldmatrix helpers (arch-portable PTX) =================
__device__ __forceinline__ uint32_t smem_u32(const void* p) {
    uint32_t a;
    asm("{ .reg .u64 t; cvta.to.shared.u64 t, %1; cvt.u32.u64 %0, t; }" : "=r"(a) : "l"(p));
    return a;
}
__device__ __forceinline__ void ldsm_x4(uint32_t* r, uint32_t addr) {
    asm volatile("ldmatrix.sync.aligned.m8n8.x4.shared.b16 {%0,%1,%2,%3}, [%4];"
        : "=r"(r[0]), "=r"(r[1]), "=r"(r[2]), "=r"(r[3]) : "r"(addr));
}
__device__ __forceinline__ void ldsm_x2(uint32_t* r, uint32_t addr) {
    asm volatile("ldmatrix.sync.aligned.m8n8.x2.shared.b16 {%0,%1}, [%2];"
        : "=r"(r[0]), "=r"(r[1]) : "r"(addr));
}
__device__ __forceinline__ void mma_f16(float* c, const uint32_t* a, const uint32_t* b) {
    asm volatile("mma.sync.aligned.m16n8k16.row.col.f32.f16.f16.f32 "
        "{%0,%1,%2,%3}, {%4,%5,%6,%7}, {%8,%9}, {%0,%1,%2,%3};"
        : "+f"(c[0]), "+f"(c[1]), "+f"(c[2]), "+f"(c[3])
        : "r"(a[0]), "r"(a[1]), "r"(a[2]), "r"(a[3]), "r"(b[0]), "r"(b[1]));
}

// ---------------- degree / normalization ----------------
__global__ void k_deg_init() {
    int i = blockIdx.x * blockDim.x + threadIdx.x;
    if (i < NN) g_deg[i] = 1;
}
__global__ void k_deg_count(const int* __restrict__ dst) {
    int e = blockIdx.x * blockDim.x + threadIdx.x;
    if (e < NE) atomicAdd(&g_deg[dst[e]], 1);
}
__global__ void k_dinv() {
    int i = blockIdx.x * blockDim.x + threadIdx.x;
    if (i < NN) {
        float d = (float)g_deg[i];
        g_dinv[i]   = rsqrtf(d);
        g_invdeg[i] = 1.0f / d;
    }
}

// ---------------- exclusive scan of in-degree -> row_ptr ----------------
__global__ void k_scan1() {
    __shared__ int sm[SCAN_B];
    int tid = threadIdx.x;
    int i = blockIdx.x * SCAN_B + tid;
    int v = (i < NN) ? (g_deg[i] - 1) : 0;
    sm[tid] = v;
    __syncthreads();
    for (int off = 1; off < SCAN_B; off <<= 1) {
        int t = (tid >= off) ? sm[tid - off] : 0;
        __syncthreads();
        sm[tid] += t;
        __syncthreads();
    }
    if (i < NN) g_rowptr[i] = sm[tid] - v;
    if (tid == SCAN_B - 1) g_bsums[blockIdx.x] = sm[tid];
}
__global__ void k_scan2() {
    __shared__ int sm[128];
    int tid = threadIdx.x;
    int v = (tid < NB_SCAN) ? g_bsums[tid] : 0;
    sm[tid] = v;
    __syncthreads();
    for (int off = 1; off < 128; off <<= 1) {
        int t = (tid >= off) ? sm[tid - off] : 0;
        __syncthreads();
        sm[tid] += t;
        __syncthreads();
    }
    if (tid < NB_SCAN) g_bsums[tid] = sm[tid] - v;
}
__global__ void k_scan3() {
    int i = blockIdx.x * blockDim.x + threadIdx.x;
    if (i < NN) {
        int r = g_rowptr[i] + g_bsums[i / SCAN_B];
        g_rowptr[i] = r;
        g_cursor[i] = r;
    }
    if (i == 0) g_rowptr[NN] = NE;
}
__global__ void k_edge_scatter(const int* __restrict__ src, const int* __restrict__ dst) {
    int e = blockIdx.x * blockDim.x + threadIdx.x;
    if (e < NE) {
        int s = src[e];
        int d = dst[e];
        int pos = atomicAdd(&g_cursor[d], 1);
        float norm = g_dinv[s] * g_dinv[d];
        g_edge[pos] = make_uint2((unsigned)s, __float_as_uint(norm));
    }
}

// ---------------- x -> fp16 A ----------------
__global__ void k_split_x(const float* __restrict__ x) {
    int i = blockIdx.x * blockDim.x + threadIdx.x;   // handles 4 floats
    if (i >= NN * HF / 4) return;
    float4 v = ((const float4*)x)[i];
    __half2 a = __floats2half2_rn(v.x, v.y);
    __half2 b = __floats2half2_rn(v.z, v.w);
    ((uint2*)g_ax)[i] = make_uint2(*(uint32_t*)&a, *(uint32_t*)&b);
}

// ---------------- W^T -> fp16 (all 4 layers) ----------------
__global__ void k_wsplit(const float* __restrict__ W0, const float* __restrict__ W1,
                         const float* __restrict__ W2, const float* __restrict__ W3) {
    int i = blockIdx.x * blockDim.x + threadIdx.x;
    if (i >= 4 * HF * HF) return;
    int l = i >> 14;
    int rem = i & 16383;
    int n = rem >> 7;        // output col
    int k = rem & 127;       // input dim
    const float* W = (l == 0) ? W0 : (l == 1) ? W1 : (l == 2) ? W2 : W3;
    g_whi[i] = __float2half_rn(W[k * HF + n]);   // layout: [l][n][k]
}

// ---------------- HMMA fp16 GEMM: g_h = A @ W ----------------
// 128x128x128 per CTA (2 CTA/SM), 256 threads = 8 warps (2x4), warp tile 64x32.
__device__ __forceinline__ void fill_tile(char* smem, int off,
                                          const void* __restrict__ g,
                                          int row0, bool clampA, int tid) {
    const uint4* src = (const uint4*)g;
#pragma unroll
    for (int it = 0; it < 8; it++) {
        int idx = it * 256 + tid;       // 0..2047 (128 rows x 16 uint4)
        int row = idx >> 4;
        int seg = idx & 15;
        int grow = clampA ? min(row0 + row, NN - 1) : row;
        uint4 v = src[grow * 16 + seg];
        *(uint4*)(smem + off + row * (TSTR * 2) + seg * 16) = v;
    }
}

__global__ __launch_bounds__(256) void k_hgemm(int l) {
    extern __shared__ char smem[];
    const int tid  = threadIdx.x;
    const int warp = tid >> 5;
    const int lane = tid & 31;
    const int wm = warp >> 2;           // 0..1  (m block of 64)
    const int wn = warp & 3;            // 0..3  (n block of 32)
    const int row0 = blockIdx.x * 128;

    fill_tile(smem, OFF_A, g_ax,               row0, true,  tid);
    fill_tile(smem, OFF_B, g_whi + l * HF * HF, 0,   false, tid);
    __syncthreads();

    const uint32_t sbase = smem_u32(smem);

    const int lgrp  = lane >> 3;        // 0..3
    const int lrow  = lane & 7;         // 0..7
    const int a_r   = (lgrp & 1) * 8 + lrow;
    const int a_k   = (lgrp >> 1) * 8;
    const int b_r   = lrow;
    const int b_k   = (lgrp & 1) * 8;

    float acc[4][4][4];
#pragma unroll
    for (int i = 0; i < 4; i++)
#pragma unroll
        for (int j = 0; j < 4; j++)
#pragma unroll
            for (int q = 0; q < 4; q++) acc[i][j][q] = 0.0f;

#pragma unroll
    for (int kc = 0; kc < 8; kc++) {
        uint32_t af[4][4], bf[4][2];
#pragma unroll
        for (int mf = 0; mf < 4; mf++) {
            int mrow = wm * 64 + mf * 16 + a_r;
            uint32_t byteoff = (uint32_t)(mrow * (TSTR * 2) + (kc * 16 + a_k) * 2);
            ldsm_x4(af[mf], sbase + OFF_A + byteoff);
        }
#pragma unroll
        for (int nf = 0; nf < 4; nf++) {
            int nrow = wn * 32 + nf * 8 + b_r;
            uint32_t byteoff = (uint32_t)(nrow * (TSTR * 2) + (kc * 16 + b_k) * 2);
            ldsm_x2(bf[nf], sbase + OFF_B + byteoff);
        }
#pragma unroll
        for (int mf = 0; mf < 4; mf++)
#pragma unroll
            for (int nf = 0; nf < 4; nf++)
                mma_f16(acc[mf][nf], af[mf], bf[nf]);
    }

    // epilogue: c frag lane l -> rows l/4 and l/4+8, cols (l%4)*2; store fp16 pairs
    const int crow = lane >> 2;
    const int ccol = (lane & 3) * 2;
#pragma unroll
    for (int mf = 0; mf < 4; mf++) {
        int r0 = row0 + wm * 64 + mf * 16 + crow;
        int r1 = r0 + 8;
#pragma unroll
        for (int nf = 0; nf < 4; nf++) {
            int c = wn * 32 + nf * 8 + ccol;
            if (r0 < NN)
                *(__half2*)&g_h[r0 * HF + c] = __floats2half2_rn(acc[mf][nf][0], acc[mf][nf][1]);
            if (r1 < NN)
                *(__half2*)&g_h[r1 * HF + c] = __floats2half2_rn(acc[mf][nf][2], acc[mf][nf][3]);
        }
    }
}

// ---------------- CSR gather aggregation + self-loop + bias + tanh ----------------
// one warp per node, lane owns 4 features (uint2 = 4 fp16); unroll-4 (R13-proven).
// Writes fp16 g_ax (next GEMM A) except last layer (fp32 for pooling).
__device__ __forceinline__ float4 h4_from_u2(uint2 u) {
    __half2 p0 = *(__half2*)&u.x;
    __half2 p1 = *(__half2*)&u.y;
    float2 f0 = __half22float2(p0);
    float2 f1 = __half22float2(p1);
    return make_float4(f0.x, f0.y, f1.x, f1.y);
}

__global__ __launch_bounds__(256) void k_agg(const float* __restrict__ bias, int last) {
    int node = blockIdx.x * 8 + (threadIdx.x >> 5);
    if (node >= NN) return;
    int lane = threadIdx.x & 31;
    const uint2* __restrict__ h2 = (const uint2*)g_h;   // row = 32 uint2

    int beg = g_rowptr[node];
    int end = g_rowptr[node + 1];

    float4 acc = make_float4(0.f, 0.f, 0.f, 0.f);
    int e = beg;
    for (; e + 3 < end; e += 4) {
        uint2 m0 = g_edge[e],     m1 = g_edge[e + 1];
        uint2 m2 = g_edge[e + 2], m3 = g_edge[e + 3];
        float4 v0 = h4_from_u2(h2[m0.x * 32 + lane]);
        float4 v1 = h4_from_u2(h2[m1.x * 32 + lane]);
        float4 v2 = h4_from_u2(h2[m2.x * 32 + lane]);
        float4 v3 = h4_from_u2(h2[m3.x * 32 + lane]);
        float w0 = __uint_as_float(m0.y), w1 = __uint_as_float(m1.y);
        float w2 = __uint_as_float(m2.y), w3 = __uint_as_float(m3.y);
        acc.x += w0 * v0.x + w1 * v1.x + w2 * v2.x + w3 * v3.x;
        acc.y += w0 * v0.y + w1 * v1.y + w2 * v2.y + w3 * v3.y;
        acc.z += w0 * v0.z + w1 * v1.z + w2 * v2.z + w3 * v3.z;
        acc.w += w0 * v0.w + w1 * v1.w + w2 * v2.w + w3 * v3.w;
    }
    for (; e < end; e++) {
        uint2 m = g_edge[e];
        float w = __uint_as_float(m.y);
        float4 v = h4_from_u2(h2[m.x * 32 + lane]);
        acc.x += w * v.x; acc.y += w * v.y; acc.z += w * v.z; acc.w += w * v.w;
    }

    float4 hs = h4_from_u2(h2[node * 32 + lane]);
    float inv = g_invdeg[node];
    float4 bb = ((const float4*)bias)[lane];
    float4 o;
    o.x = tanhf(acc.x + inv * hs.x + bb.x);
    o.y = tanhf(acc.y + inv * hs.y + bb.y);
    o.z = tanhf(acc.z + inv * hs.z + bb.z);
    o.w = tanhf(acc.w + inv * hs.w + bb.w);

    if (last) {
        ((float4*)g_xB)[node * 32 + lane] = o;
    } else {
        __half2 a = __floats2half2_rn(o.x, o.y);
        __half2 b = __floats2half2_rn(o.z, o.w);
        ((uint2*)g_ax)[node * 32 + lane] = make_uint2(*(uint32_t*)&a, *(uint32_t*)&b);
    }
}

// ---------------- pooling ----------------
__global__ void k_pool_init() {
    int i = blockIdx.x * blockDim.x + threadIdx.x;
    if (i < NG * HF) {
        g_gmax[i] = -INFINITY;
        g_gsum[i] = 0.0f;
    }
    if (i < NG) g_gcnt[i] = 0;
}

__device__ __forceinline__ void atomicMaxF(float* addr, float v) {
    if (v >= 0.0f) atomicMax((int*)addr, __float_as_int(v));
    else           atomicMin((unsigned int*)addr, __float_as_uint(v));
}

__global__ __launch_bounds__(128) void k_pool(const int* __restrict__ batch) {
    const float* __restrict__ x = g_xB;
    int t  = threadIdx.x;
    int n0 = blockIdx.x * POOL_CH;
    if (n0 >= NN) return;
    int n1 = min(n0 + POOL_CH, NN);

    int cur = -1;
    float rmax = -INFINITY, rsum = 0.0f;
    int rcnt = 0;
    for (int n = n0; n < n1; n++) {
        int g = batch[n];
        if (g != cur) {
            if (cur >= 0) {
                atomicMaxF(&g_gmax[cur * HF + t], rmax);
                atomicAdd(&g_gsum[cur * HF + t], rsum);
                if (t == 0) atomicAdd(&g_gcnt[cur], rcnt);
            }
            cur = g; rmax = -INFINITY; rsum = 0.0f; rcnt = 0;
        }
        float v = x[n * HF + t];
        rmax = fmaxf(rmax, v);
        rsum += v;
        rcnt++;
    }
    if (cur >= 0) {
        atomicMaxF(&g_gmax[cur * HF + t], rmax);
        atomicAdd(&g_gsum[cur * HF + t], rsum);
        if (t == 0) atomicAdd(&g_gcnt[cur], rcnt);
    }
}

// ---------------- finalize ----------------
__global__ __launch_bounds__(256) void k_finalize(const float* __restrict__ Wout,
                                                  const float* __restrict__ bout,
                                                  float* __restrict__ dout, int out_size) {
    __shared__ float p[2 * HF];
    int g = blockIdx.x;
    int t = threadIdx.x;

    float val;
    if (t < HF) {
        val = g_gmax[g * HF + t];
    } else {
        float c = fmaxf((float)g_gcnt[g], 1.0f);
        val = g_gsum[g * HF + (t - HF)] / c;
    }
    p[t] = val;
    int pidx = NG * NC + g * (2 * HF) + t;
    if (pidx < out_size) dout[pidx] = val;
    __syncthreads();

    if (t < NC) {
        float s = bout[t];
#pragma unroll 8
        for (int j = 0; j < 2 * HF; j++) s += p[j] * Wout[j * NC + t];
        int oidx = g * NC + t;
        if (oidx < out_size) dout[oidx] = s;
    }
}

// ---------------- launch ----------------
extern "C" void kernel_launch(void* const* d_in, const int* in_sizes, int n_in,
                              void* d_out, int out_size) {
    const float* x     = (const float*)d_in[0];
    const int*   ei    = (const int*)  d_in[1];
    const int*   batch = (const int*)  d_in[2];
    const float* W0 = (const float*)d_in[3];  const float* b0 = (const float*)d_in[4];
    const float* W1 = (const float*)d_in[5];  const float* b1 = (const float*)d_in[6];
    const float* W2 = (const float*)d_in[7];  const float* b2 = (const float*)d_in[8];
    const float* W3 = (const float*)d_in[9];  const float* b3 = (const float*)d_in[10];
    const float* Wout = (const float*)d_in[11];
    const float* bout = (const float*)d_in[12];
    float* dout = (float*)d_out;

    const int* src = ei;
    const int* dst = ei + NE;

    const int TB = 256;
    const int gN = (NN + TB - 1) / TB;
    const int gE = (NE + TB - 1) / TB;
    const int gGemm = (NN + 127) / 128;       // 782
    const int gAgg  = (NN + 7) / 8;
    const int gPool = (NN + POOL_CH - 1) / POOL_CH;

    // Idempotent, capture-safe (not a stream op).
    cudaFuncSetAttribute(k_hgemm, cudaFuncAttributeMaxDynamicSharedMemorySize, SMB);

    // ---- graph preprocessing ----
    k_deg_init<<<gN, TB>>>();
    k_deg_count<<<gE, TB>>>(dst);
    k_dinv<<<gN, TB>>>();
    k_scan1<<<NB_SCAN, SCAN_B>>>();
    k_scan2<<<1, 128>>>();
    k_scan3<<<gN, TB>>>();
    k_edge_scatter<<<gE, TB>>>(src, dst);

    // ---- precision prep ----
    k_split_x<<<(NN * HF / 4 + TB - 1) / TB, TB>>>(x);
    k_wsplit<<<(4 * HF * HF + TB - 1) / TB, TB>>>(W0, W1, W2, W3);

    // ---- 4 GCN layers ----
    const float* biases[4] = {b0, b1, b2, b3};
    for (int l = 0; l < 4; l++) {
        k_hgemm<<<gGemm, 256, SMB>>>(l);
        k_agg<<<gAgg, 256>>>(biases[l], l == 3 ? 1 : 0);
    }

    // ---- pooling + head ----
    k_pool_init<<<(NG * HF + TB - 1) / TB, TB>>>();
    k_pool<<<gPool, 128>>>(batch);
    k_finalize<<<NG, 256>>>(Wout, bout, dout, out_size);
}

// round 16
// speedup vs baseline: 1.1562x; 1.0431x over previous
#include <cuda_runtime.h>
#include <cuda_bf16.h>
#include <cuda_fp16.h>
#include <cstdint>
#include <math.h>

#define NN 100000
#define NE 1600000
#define HF 128
#define NG 64
#define NC 10
#define SCAN_B 1024
#define NB_SCAN ((NN + SCAN_B - 1) / SCAN_B)   // 98
#define POOL_CH 256

// GEMM smem tile geometry: 128 rows x 128 fp16, padded stride 136 elems (272B)
#define TSTR 136
#define TILE_BYTES (128 * TSTR * 2)            // 34816
#define OFF_A  0
#define OFF_B  (TILE_BYTES)
#define SMB    (2 * TILE_BYTES)                // 69632 -> 2 CTA/SM

// ---------------- scratch (static device globals; no allocation) ----------------
__device__ __half g_h  [NN * HF];             // h' = dinv * (A @ W)  (fp16 rows, 256B)
__device__ __half g_ax [NN * HF];             // activation (GEMM A input, fp16)
__device__ __half g_whi[4 * HF * HF];         // W^T fp16 per layer, layout [l][n][k]
__device__ float g_xB [NN * HF];              // final layer fp32 output (for pooling)
__device__ int   g_deg   [NN];
__device__ float g_dinv  [NN];
__device__ int   g_rowptr[NN + 1];
__device__ int   g_cursor[NN];
__device__ int   g_esrc  [NE];                // edge src only (weights folded into h')
__device__ int   g_bsums [128];
__device__ float g_gmax  [NG * HF];
__device__ float g_gsum  [NG * HF];
__device__ int   g_gcnt  [NG];

// ================= mma.sync / ldmatrix helpers (arch-portable PTX) =================
__device__ __forceinline__ uint32_t smem_u32(const void* p) {
    uint32_t a;
    asm("{ .reg .u64 t; cvta.to.shared.u64 t, %1; cvt.u32.u64 %0, t; }" : "=r"(a) : "l"(p));
    return a;
}
__device__ __forceinline__ void ldsm_x4(uint32_t* r, uint32_t addr) {
    asm volatile("ldmatrix.sync.aligned.m8n8.x4.shared.b16 {%0,%1,%2,%3}, [%4];"
        : "=r"(r[0]), "=r"(r[1]), "=r"(r[2]), "=r"(r[3]) : "r"(addr));
}
__device__ __forceinline__ void ldsm_x2(uint32_t* r, uint32_t addr) {
    asm volatile("ldmatrix.sync.aligned.m8n8.x2.shared.b16 {%0,%1}, [%2];"
        : "=r"(r[0]), "=r"(r[1]) : "r"(addr));
}
__device__ __forceinline__ void mma_f16(float* c, const uint32_t* a, const uint32_t* b) {
    asm volatile("mma.sync.aligned.m16n8k16.row.col.f32.f16.f16.f32 "
        "{%0,%1,%2,%3}, {%4,%5,%6,%7}, {%8,%9}, {%0,%1,%2,%3};"
        : "+f"(c[0]), "+f"(c[1]), "+f"(c[2]), "+f"(c[3])
        : "r"(a[0]), "r"(a[1]), "r"(a[2]), "r"(a[3]), "r"(b[0]), "r"(b[1]));
}

// ---------------- degree / normalization ----------------
__global__ void k_deg_init() {
    int i = blockIdx.x * blockDim.x + threadIdx.x;
    if (i < NN) g_deg[i] = 1;
}
__global__ void k_deg_count(const int* __restrict__ dst) {
    int e = blockIdx.x * blockDim.x + threadIdx.x;
    if (e < NE) atomicAdd(&g_deg[dst[e]], 1);
}

// ---------------- exclusive scan of in-degree -> row_ptr (+ dinv fused) ----------------
__global__ void k_scan1() {
    __shared__ int sm[SCAN_B];
    int tid = threadIdx.x;
    int i = blockIdx.x * SCAN_B + tid;
    int dval = (i < NN) ? g_deg[i] : 1;
    int v = dval - 1;
    sm[tid] = v;
    if (i < NN) g_dinv[i] = rsqrtf((float)dval);   // fused dinv
    __syncthreads();
    for (int off = 1; off < SCAN_B; off <<= 1) {
        int t = (tid >= off) ? sm[tid - off] : 0;
        __syncthreads();
        sm[tid] += t;
        __syncthreads();
    }
    if (i < NN) g_rowptr[i] = sm[tid] - v;
    if (tid == SCAN_B - 1) g_bsums[blockIdx.x] = sm[tid];
}
__global__ void k_scan2() {
    __shared__ int sm[128];
    int tid = threadIdx.x;
    int v = (tid < NB_SCAN) ? g_bsums[tid] : 0;
    sm[tid] = v;
    __syncthreads();
    for (int off = 1; off < 128; off <<= 1) {
        int t = (tid >= off) ? sm[tid - off] : 0;
        __syncthreads();
        sm[tid] += t;
        __syncthreads();
    }
    if (tid < NB_SCAN) g_bsums[tid] = sm[tid] - v;
}
__global__ void k_scan3() {
    int i = blockIdx.x * blockDim.x + threadIdx.x;
    if (i < NN) {
        int r = g_rowptr[i] + g_bsums[i / SCAN_B];
        g_rowptr[i] = r;
        g_cursor[i] = r;
    }
    if (i == 0) g_rowptr[NN] = NE;
}
__global__ void k_edge_scatter(const int* __restrict__ src, const int* __restrict__ dst) {
    int e = blockIdx.x * blockDim.x + threadIdx.x;
    if (e < NE) {
        int s = src[e];
        int d = dst[e];
        int pos = atomicAdd(&g_cursor[d], 1);
        g_esrc[pos] = s;                 // no weight: folded into h' via dinv prescale
    }
}

// ---------------- x -> fp16 A ----------------
__global__ void k_split_x(const float* __restrict__ x) {
    int i = blockIdx.x * blockDim.x + threadIdx.x;   // handles 4 floats
    if (i >= NN * HF / 4) return;
    float4 v = ((const float4*)x)[i];
    __half2 a = __floats2half2_rn(v.x, v.y);
    __half2 b = __floats2half2_rn(v.z, v.w);
    ((uint2*)g_ax)[i] = make_uint2(*(uint32_t*)&a, *(uint32_t*)&b);
}

// ---------------- W^T -> fp16 (all 4 layers) ----------------
__global__ void k_wsplit(const float* __restrict__ W0, const float* __restrict__ W1,
                         const float* __restrict__ W2, const float* __restrict__ W3) {
    int i = blockIdx.x * blockDim.x + threadIdx.x;
    if (i >= 4 * HF * HF) return;
    int l = i >> 14;
    int rem = i & 16383;
    int n = rem >> 7;        // output col
    int k = rem & 127;       // input dim
    const float* W = (l == 0) ? W0 : (l == 1) ? W1 : (l == 2) ? W2 : W3;
    g_whi[i] = __float2half_rn(W[k * HF + n]);   // layout: [l][n][k]
}

// ---------------- HMMA fp16 GEMM: g_h = dinv ⊙ (A @ W) ----------------
// 128x128x128 per CTA (2 CTA/SM), 256 threads = 8 warps (2x4), warp tile 64x32.
__device__ __forceinline__ void fill_tile(char* smem, int off,
                                          const void* __restrict__ g,
                                          int row0, bool clampA, int tid) {
    const uint4* src = (const uint4*)g;
#pragma unroll
    for (int it = 0; it < 8; it++) {
        int idx = it * 256 + tid;       // 0..2047 (128 rows x 16 uint4)
        int row = idx >> 4;
        int seg = idx & 15;
        int grow = clampA ? min(row0 + row, NN - 1) : row;
        uint4 v = src[grow * 16 + seg];
        *(uint4*)(smem + off + row * (TSTR * 2) + seg * 16) = v;
    }
}

__global__ __launch_bounds__(256) void k_hgemm(int l) {
    extern __shared__ char smem[];
    const int tid  = threadIdx.x;
    const int warp = tid >> 5;
    const int lane = tid & 31;
    const int wm = warp >> 2;           // 0..1  (m block of 64)
    const int wn = warp & 3;            // 0..3  (n block of 32)
    const int row0 = blockIdx.x * 128;

    fill_tile(smem, OFF_A, g_ax,               row0, true,  tid);
    fill_tile(smem, OFF_B, g_whi + l * HF * HF, 0,   false, tid);
    __syncthreads();

    const uint32_t sbase = smem_u32(smem);

    const int lgrp  = lane >> 3;        // 0..3
    const int lrow  = lane & 7;         // 0..7
    const int a_r   = (lgrp & 1) * 8 + lrow;
    const int a_k   = (lgrp >> 1) * 8;
    const int b_r   = lrow;
    const int b_k   = (lgrp & 1) * 8;

    float acc[4][4][4];
#pragma unroll
    for (int i = 0; i < 4; i++)
#pragma unroll
        for (int j = 0; j < 4; j++)
#pragma unroll
            for (int q = 0; q < 4; q++) acc[i][j][q] = 0.0f;

#pragma unroll
    for (int kc = 0; kc < 8; kc++) {
        uint32_t af[4][4], bf[4][2];
#pragma unroll
        for (int mf = 0; mf < 4; mf++) {
            int mrow = wm * 64 + mf * 16 + a_r;
            uint32_t byteoff = (uint32_t)(mrow * (TSTR * 2) + (kc * 16 + a_k) * 2);
            ldsm_x4(af[mf], sbase + OFF_A + byteoff);
        }
#pragma unroll
        for (int nf = 0; nf < 4; nf++) {
            int nrow = wn * 32 + nf * 8 + b_r;
            uint32_t byteoff = (uint32_t)(nrow * (TSTR * 2) + (kc * 16 + b_k) * 2);
            ldsm_x2(bf[nf], sbase + OFF_B + byteoff);
        }
#pragma unroll
        for (int mf = 0; mf < 4; mf++)
#pragma unroll
            for (int nf = 0; nf < 4; nf++)
                mma_f16(acc[mf][nf], af[mf], bf[nf]);
    }

    // epilogue: scale row r by dinv[r], store fp16 pairs
    const int crow = lane >> 2;
    const int ccol = (lane & 3) * 2;
#pragma unroll
    for (int mf = 0; mf < 4; mf++) {
        int r0 = row0 + wm * 64 + mf * 16 + crow;
        int r1 = r0 + 8;
        float dv0 = (r0 < NN) ? g_dinv[r0] : 0.0f;
        float dv1 = (r1 < NN) ? g_dinv[r1] : 0.0f;
#pragma unroll
        for (int nf = 0; nf < 4; nf++) {
            int c = wn * 32 + nf * 8 + ccol;
            if (r0 < NN)
                *(__half2*)&g_h[r0 * HF + c] =
                    __floats2half2_rn(dv0 * acc[mf][nf][0], dv0 * acc[mf][nf][1]);
            if (r1 < NN)
                *(__half2*)&g_h[r1 * HF + c] =
                    __floats2half2_rn(dv1 * acc[mf][nf][2], dv1 * acc[mf][nf][3]);
        }
    }
}

// ---------------- CSR gather aggregation + self-loop + bias + tanh ----------------
// one warp per node, lane owns 4 features (uint2 = 4 fp16); unroll-4.
// h' rows are pre-scaled by dinv[src], so the gather is an unweighted sum:
//   o = tanh(dinv[dst] * (sum h'[src] + h'[dst]) + b)
__device__ __forceinline__ float4 h4_from_u2(uint2 u) {
    __half2 p0 = *(__half2*)&u.x;
    __half2 p1 = *(__half2*)&u.y;
    float2 f0 = __half22float2(p0);
    float2 f1 = __half22float2(p1);
    return make_float4(f0.x, f0.y, f1.x, f1.y);
}

__global__ __launch_bounds__(256) void k_agg(const float* __restrict__ bias, int last) {
    int node = blockIdx.x * 8 + (threadIdx.x >> 5);
    if (node >= NN) return;
    int lane = threadIdx.x & 31;
    const uint2* __restrict__ h2 = (const uint2*)g_h;   // row = 32 uint2

    int beg = g_rowptr[node];
    int end = g_rowptr[node + 1];

    float4 acc = make_float4(0.f, 0.f, 0.f, 0.f);
    int e = beg;
    for (; e + 3 < end; e += 4) {
        int s0 = g_esrc[e],     s1 = g_esrc[e + 1];
        int s2 = g_esrc[e + 2], s3 = g_esrc[e + 3];
        float4 v0 = h4_from_u2(h2[s0 * 32 + lane]);
        float4 v1 = h4_from_u2(h2[s1 * 32 + lane]);
        float4 v2 = h4_from_u2(h2[s2 * 32 + lane]);
        float4 v3 = h4_from_u2(h2[s3 * 32 + lane]);
        acc.x += v0.x + v1.x + v2.x + v3.x;
        acc.y += v0.y + v1.y + v2.y + v3.y;
        acc.z += v0.z + v1.z + v2.z + v3.z;
        acc.w += v0.w + v1.w + v2.w + v3.w;
    }
    for (; e < end; e++) {
        float4 v = h4_from_u2(h2[g_esrc[e] * 32 + lane]);
        acc.x += v.x; acc.y += v.y; acc.z += v.z; acc.w += v.w;
    }

    float4 hs = h4_from_u2(h2[node * 32 + lane]);
    float dv = g_dinv[node];
    float4 bb = ((const float4*)bias)[lane];
    float4 o;
    o.x = tanhf(dv * (acc.x + hs.x) + bb.x);
    o.y = tanhf(dv * (acc.y + hs.y) + bb.y);
    o.z = tanhf(dv * (acc.z + hs.z) + bb.z);
    o.w = tanhf(dv * (acc.w + hs.w) + bb.w);

    if (last) {
        ((float4*)g_xB)[node * 32 + lane] = o;
    } else {
        __half2 a = __floats2half2_rn(o.x, o.y);
        __half2 b = __floats2half2_rn(o.z, o.w);
        ((uint2*)g_ax)[node * 32 + lane] = make_uint2(*(uint32_t*)&a, *(uint32_t*)&b);
    }
}

// ---------------- pooling ----------------
__global__ void k_pool_init() {
    int i = blockIdx.x * blockDim.x + threadIdx.x;
    if (i < NG * HF) {
        g_gmax[i] = -INFINITY;
        g_gsum[i] = 0.0f;
    }
    if (i < NG) g_gcnt[i] = 0;
}

__device__ __forceinline__ void atomicMaxF(float* addr, float v) {
    if (v >= 0.0f) atomicMax((int*)addr, __float_as_int(v));
    else           atomicMin((unsigned int*)addr, __float_as_uint(v));
}

__global__ __launch_bounds__(128) void k_pool(const int* __restrict__ batch) {
    const float* __restrict__ x = g_xB;
    int t  = threadIdx.x;
    int n0 = blockIdx.x * POOL_CH;
    if (n0 >= NN) return;
    int n1 = min(n0 + POOL_CH, NN);

    int cur = -1;
    float rmax = -INFINITY, rsum = 0.0f;
    int rcnt = 0;
    for (int n = n0; n < n1; n++) {
        int g = batch[n];
        if (g != cur) {
            if (cur >= 0) {
                atomicMaxF(&g_gmax[cur * HF + t], rmax);
                atomicAdd(&g_gsum[cur * HF + t], rsum);
                if (t == 0) atomicAdd(&g_gcnt[cur], rcnt);
            }
            cur = g; rmax = -INFINITY; rsum = 0.0f; rcnt = 0;
        }
        float v = x[n * HF + t];
        rmax = fmaxf(rmax, v);
        rsum += v;
        rcnt++;
    }
    if (cur >= 0) {
        atomicMaxF(&g_gmax[cur * HF + t], rmax);
        atomicAdd(&g_gsum[cur * HF + t], rsum);
        if (t == 0) atomicAdd(&g_gcnt[cur], rcnt);
    }
}

// ---------------- finalize ----------------
__global__ __launch_bounds__(256) void k_finalize(const float* __restrict__ Wout,
                                                  const float* __restrict__ bout,
                                                  float* __restrict__ dout, int out_size) {
    __shared__ float p[2 * HF];
    int g = blockIdx.x;
    int t = threadIdx.x;

    float val;
    if (t < HF) {
        val = g_gmax[g * HF + t];
    } else {
        float c = fmaxf((float)g_gcnt[g], 1.0f);
        val = g_gsum[g * HF + (t - HF)] / c;
    }
    p[t] = val;
    int pidx = NG * NC + g * (2 * HF) + t;
    if (pidx < out_size) dout[pidx] = val;
    __syncthreads();

    if (t < NC) {
        float s = bout[t];
#pragma unroll 8
        for (int j = 0; j < 2 * HF; j++) s += p[j] * Wout[j * NC + t];
        int oidx = g * NC + t;
        if (oidx < out_size) dout[oidx] = s;
    }
}

// ---------------- launch ----------------
extern "C" void kernel_launch(void* const* d_in, const int* in_sizes, int n_in,
                              void* d_out, int out_size) {
    const float* x     = (const float*)d_in[0];
    const int*   ei    = (const int*)  d_in[1];
    const int*   batch = (const int*)  d_in[2];
    const float* W0 = (const float*)d_in[3];  const float* b0 = (const float*)d_in[4];
    const float* W1 = (const float*)d_in[5];  const float* b1 = (const float*)d_in[6];
    const float* W2 = (const float*)d_in[7];  const float* b2 = (const float*)d_in[8];
    const float* W3 = (const float*)d_in[9];  const float* b3 = (const float*)d_in[10];
    const float* Wout = (const float*)d_in[11];
    const float* bout = (const float*)d_in[12];
    float* dout = (float*)d_out;

    const int* src = ei;
    const int* dst = ei + NE;

    const int TB = 256;
    const int gN = (NN + TB - 1) / TB;
    const int gE = (NE + TB - 1) / TB;
    const int gGemm = (NN + 127) / 128;       // 782
    const int gAgg  = (NN + 7) / 8;
    const int gPool = (NN + POOL_CH - 1) / POOL_CH;

    // Idempotent, capture-safe (not a stream op).
    cudaFuncSetAttribute(k_hgemm, cudaFuncAttributeMaxDynamicSharedMemorySize, SMB);

    // ---- graph preprocessing ----
    k_deg_init<<<gN, TB>>>();
    k_deg_count<<<gE, TB>>>(dst);
    k_scan1<<<NB_SCAN, SCAN_B>>>();           // also computes dinv
    k_scan2<<<1, 128>>>();
    k_scan3<<<gN, TB>>>();
    k_edge_scatter<<<gE, TB>>>(src, dst);

    // ---- precision prep ----
    k_split_x<<<(NN * HF / 4 + TB - 1) / TB, TB>>>(x);
    k_wsplit<<<(4 * HF * HF + TB - 1) / TB, TB>>>(W0, W1, W2, W3);

    // ---- 4 GCN layers ----
    const float* biases[4] = {b0, b1, b2, b3};
    for (int l = 0; l < 4; l++) {
        k_hgemm<<<gGemm, 256, SMB>>>(l);
        k_agg<<<gAgg, 256>>>(biases[l], l == 3 ? 1 : 0);
    }

    // ---- pooling + head ----
    k_pool_init<<<(NG * HF + TB - 1) / TB, TB>>>();
    k_pool<<<gPool, 128>>>(batch);
    k_finalize<<<NG, 256>>>(Wout, bout, dout, out_size);
}

// round 17
// speedup vs baseline: 1.1611x; 1.0043x over previous
#include <cuda_runtime.h>
#include <cuda_bf16.h>
#include <cuda_fp16.h>
#include <cstdint>
#include <math.h>

#define NN 100000
#define NE 1600000
#define HF 128
#define NG 64
#define NC 10
#define SCAN_B 1024
#define NB_SCAN ((NN + SCAN_B - 1) / SCAN_B)   // 98
#define POOL_CH 256

// GEMM smem tile geometry: 128 rows x 128 fp16, padded stride 136 elems (272B)
#define TSTR 136
#define TILE_BYTES (128 * TSTR * 2)            // 34816
#define OFF_A  0
#define OFF_B  (TILE_BYTES)
#define SMB    (2 * TILE_BYTES)                // 69632 -> 2 CTA/SM

// ---------------- scratch (static device globals; no allocation) ----------------
__device__ __half g_h  [NN * HF];             // h' = dinv * (A @ W)  (fp16 rows, 256B)
__device__ __half g_ax [NN * HF];             // activation (GEMM A input, fp16)
__device__ __half g_whi[4 * HF * HF];         // W^T fp16 per layer, layout [l][n][k]
__device__ float g_xB [NN * HF];              // final layer fp32 output (for pooling)
__device__ int   g_deg   [NN];
__device__ float g_dinv  [NN];
__device__ int   g_rowptr[NN + 1];
__device__ int   g_cursor[NN];
__device__ int   g_esrc  [NE];                // edge src only (weights folded into h')
__device__ int   g_bsums [128];
__device__ float g_gmax  [NG * HF];
__device__ float g_gsum  [NG * HF];
__device__ int   g_gcnt  [NG];

// ================= mma.sync / ldmatrix helpers (arch-portable PTX) =================
__device__ __forceinline__ uint32_t smem_u32(const void* p) {
    uint32_t a;
    asm("{ .reg .u64 t; cvta.to.shared.u64 t, %1; cvt.u32.u64 %0, t; }" : "=r"(a) : "l"(p));
    return a;
}
__device__ __forceinline__ void ldsm_x4(uint32_t* r, uint32_t addr) {
    asm volatile("ldmatrix.sync.aligned.m8n8.x4.shared.b16 {%0,%1,%2,%3}, [%4];"
        : "=r"(r[0]), "=r"(r[1]), "=r"(r[2]), "=r"(r[3]) : "r"(addr));
}
__device__ __forceinline__ void ldsm_x2(uint32_t* r, uint32_t addr) {
    asm volatile("ldmatrix.sync.aligned.m8n8.x2.shared.b16 {%0,%1}, [%2];"
        : "=r"(r[0]), "=r"(r[1]) : "r"(addr));
}
__device__ __forceinline__ void mma_f16(float* c, const uint32_t* a, const uint32_t* b) {
    asm volatile("mma.sync.aligned.m16n8k16.row.col.f32.f16.f16.f32 "
        "{%0,%1,%2,%3}, {%4,%5,%6,%7}, {%8,%9}, {%0,%1,%2,%3};"
        : "+f"(c[0]), "+f"(c[1]), "+f"(c[2]), "+f"(c[3])
        : "r"(a[0]), "r"(a[1]), "r"(a[2]), "r"(a[3]), "r"(b[0]), "r"(b[1]));
}

// ---------------- degree / normalization ----------------
__global__ void k_deg_init() {
    int i = blockIdx.x * blockDim.x + threadIdx.x;
    if (i < NN) g_deg[i] = 1;
}
// 4 edges per thread (int4)
__global__ void k_deg_count(const int* __restrict__ dst) {
    int i = blockIdx.x * blockDim.x + threadIdx.x;
    if (i < NE / 4) {
        int4 d = ((const int4*)dst)[i];
        atomicAdd(&g_deg[d.x], 1);
        atomicAdd(&g_deg[d.y], 1);
        atomicAdd(&g_deg[d.z], 1);
        atomicAdd(&g_deg[d.w], 1);
    }
}

// ---------------- exclusive scan of in-degree -> row_ptr (+ dinv fused) ----------------
__global__ void k_scan1() {
    __shared__ int sm[SCAN_B];
    int tid = threadIdx.x;
    int i = blockIdx.x * SCAN_B + tid;
    int dval = (i < NN) ? g_deg[i] : 1;
    int v = dval - 1;
    sm[tid] = v;
    if (i < NN) g_dinv[i] = rsqrtf((float)dval);   // fused dinv
    __syncthreads();
    for (int off = 1; off < SCAN_B; off <<= 1) {
        int t = (tid >= off) ? sm[tid - off] : 0;
        __syncthreads();
        sm[tid] += t;
        __syncthreads();
    }
    if (i < NN) g_rowptr[i] = sm[tid] - v;
    if (tid == SCAN_B - 1) g_bsums[blockIdx.x] = sm[tid];
}
// scan2 merged in: every block redundantly scans the 98 block sums in smem
__global__ void k_scan3() {
    __shared__ int pref[128];
    __shared__ int excl[128];
    int tid = threadIdx.x;
    int v = 0;
    if (tid < 128) {
        v = (tid < NB_SCAN) ? g_bsums[tid] : 0;
        pref[tid] = v;
    }
    __syncthreads();
    for (int off = 1; off < 128; off <<= 1) {
        int t = 0;
        if (tid < 128 && tid >= off) t = pref[tid - off];
        __syncthreads();
        if (tid < 128) pref[tid] += t;
        __syncthreads();
    }
    if (tid < 128) excl[tid] = pref[tid] - v;   // exclusive block offsets
    __syncthreads();

    int i = blockIdx.x * blockDim.x + tid;
    if (i < NN) {
        int r = g_rowptr[i] + excl[i / SCAN_B];
        g_rowptr[i] = r;
        g_cursor[i] = r;
    }
    if (i == 0) g_rowptr[NN] = NE;
}
// 4 edges per thread (two int4 loads)
__global__ void k_edge_scatter(const int* __restrict__ src, const int* __restrict__ dst) {
    int i = blockIdx.x * blockDim.x + threadIdx.x;
    if (i < NE / 4) {
        int4 s = ((const int4*)src)[i];
        int4 d = ((const int4*)dst)[i];
        int p;
        p = atomicAdd(&g_cursor[d.x], 1); g_esrc[p] = s.x;
        p = atomicAdd(&g_cursor[d.y], 1); g_esrc[p] = s.y;
        p = atomicAdd(&g_cursor[d.z], 1); g_esrc[p] = s.z;
        p = atomicAdd(&g_cursor[d.w], 1); g_esrc[p] = s.w;
    }
}

// ---------------- x -> fp16 A ----------------
__global__ void k_split_x(const float* __restrict__ x) {
    int i = blockIdx.x * blockDim.x + threadIdx.x;   // handles 4 floats
    if (i >= NN * HF / 4) return;
    float4 v = ((const float4*)x)[i];
    __half2 a = __floats2half2_rn(v.x, v.y);
    __half2 b = __floats2half2_rn(v.z, v.w);
    ((uint2*)g_ax)[i] = make_uint2(*(uint32_t*)&a, *(uint32_t*)&b);
}

// ---------------- W^T -> fp16 (all 4 layers) ----------------
__global__ void k_wsplit(const float* __restrict__ W0, const float* __restrict__ W1,
                         const float* __restrict__ W2, const float* __restrict__ W3) {
    int i = blockIdx.x * blockDim.x + threadIdx.x;
    if (i >= 4 * HF * HF) return;
    int l = i >> 14;
    int rem = i & 16383;
    int n = rem >> 7;        // output col
    int k = rem & 127;       // input dim
    const float* W = (l == 0) ? W0 : (l == 1) ? W1 : (l == 2) ? W2 : W3;
    g_whi[i] = __float2half_rn(W[k * HF + n]);   // layout: [l][n][k]
}

// ---------------- HMMA fp16 GEMM: g_h = dinv ⊙ (A @ W) ----------------
// 128x128x128 per CTA (2 CTA/SM), 256 threads = 8 warps (2x4), warp tile 64x32.
__device__ __forceinline__ void fill_tile(char* smem, int off,
                                          const void* __restrict__ g,
                                          int row0, bool clampA, int tid) {
    const uint4* src = (const uint4*)g;
#pragma unroll
    for (int it = 0; it < 8; it++) {
        int idx = it * 256 + tid;       // 0..2047 (128 rows x 16 uint4)
        int row = idx >> 4;
        int seg = idx & 15;
        int grow = clampA ? min(row0 + row, NN - 1) : row;
        uint4 v = src[grow * 16 + seg];
        *(uint4*)(smem + off + row * (TSTR * 2) + seg * 16) = v;
    }
}

__global__ __launch_bounds__(256) void k_hgemm(int l) {
    extern __shared__ char smem[];
    const int tid  = threadIdx.x;
    const int warp = tid >> 5;
    const int lane = tid & 31;
    const int wm = warp >> 2;           // 0..1  (m block of 64)
    const int wn = warp & 3;            // 0..3  (n block of 32)
    const int row0 = blockIdx.x * 128;

    fill_tile(smem, OFF_A, g_ax,               row0, true,  tid);
    fill_tile(smem, OFF_B, g_whi + l * HF * HF, 0,   false, tid);
    __syncthreads();

    const uint32_t sbase = smem_u32(smem);

    const int lgrp  = lane >> 3;        // 0..3
    const int lrow  = lane & 7;         // 0..7
    const int a_r   = (lgrp & 1) * 8 + lrow;
    const int a_k   = (lgrp >> 1) * 8;
    const int b_r   = lrow;
    const int b_k   = (lgrp & 1) * 8;

    float acc[4][4][4];
#pragma unroll
    for (int i = 0; i < 4; i++)
#pragma unroll
        for (int j = 0; j < 4; j++)
#pragma unroll
            for (int q = 0; q < 4; q++) acc[i][j][q] = 0.0f;

#pragma unroll
    for (int kc = 0; kc < 8; kc++) {
        uint32_t af[4][4], bf[4][2];
#pragma unroll
        for (int mf = 0; mf < 4; mf++) {
            int mrow = wm * 64 + mf * 16 + a_r;
            uint32_t byteoff = (uint32_t)(mrow * (TSTR * 2) + (kc * 16 + a_k) * 2);
            ldsm_x4(af[mf], sbase + OFF_A + byteoff);
        }
#pragma unroll
        for (int nf = 0; nf < 4; nf++) {
            int nrow = wn * 32 + nf * 8 + b_r;
            uint32_t byteoff = (uint32_t)(nrow * (TSTR * 2) + (kc * 16 + b_k) * 2);
            ldsm_x2(bf[nf], sbase + OFF_B + byteoff);
        }
#pragma unroll
        for (int mf = 0; mf < 4; mf++)
#pragma unroll
            for (int nf = 0; nf < 4; nf++)
                mma_f16(acc[mf][nf], af[mf], bf[nf]);
    }

    // epilogue: scale row r by dinv[r], store fp16 pairs
    const int crow = lane >> 2;
    const int ccol = (lane & 3) * 2;
#pragma unroll
    for (int mf = 0; mf < 4; mf++) {
        int r0 = row0 + wm * 64 + mf * 16 + crow;
        int r1 = r0 + 8;
        float dv0 = (r0 < NN) ? g_dinv[r0] : 0.0f;
        float dv1 = (r1 < NN) ? g_dinv[r1] : 0.0f;
#pragma unroll
        for (int nf = 0; nf < 4; nf++) {
            int c = wn * 32 + nf * 8 + ccol;
            if (r0 < NN)
                *(__half2*)&g_h[r0 * HF + c] =
                    __floats2half2_rn(dv0 * acc[mf][nf][0], dv0 * acc[mf][nf][1]);
            if (r1 < NN)
                *(__half2*)&g_h[r1 * HF + c] =
                    __floats2half2_rn(dv1 * acc[mf][nf][2], dv1 * acc[mf][nf][3]);
        }
    }
}

// ---------------- CSR gather aggregation + self-loop + bias + tanh ----------------
// one warp per node, lane owns 4 features (uint2 = 4 fp16); unroll-4.
// 512-thread blocks (16 nodes) -> oe=4 CTAs/SM: cuts cross-CTA L1tex-queue spread.
__device__ __forceinline__ float4 h4_from_u2(uint2 u) {
    __half2 p0 = *(__half2*)&u.x;
    __half2 p1 = *(__half2*)&u.y;
    float2 f0 = __half22float2(p0);
    float2 f1 = __half22float2(p1);
    return make_float4(f0.x, f0.y, f1.x, f1.y);
}

__global__ __launch_bounds__(512) void k_agg(const float* __restrict__ bias, int last) {
    int node = blockIdx.x * 16 + (threadIdx.x >> 5);
    if (node >= NN) return;
    int lane = threadIdx.x & 31;
    const uint2* __restrict__ h2 = (const uint2*)g_h;   // row = 32 uint2

    int beg = g_rowptr[node];
    int end = g_rowptr[node + 1];

    float4 acc = make_float4(0.f, 0.f, 0.f, 0.f);
    int e = beg;
    for (; e + 3 < end; e += 4) {
        int s0 = g_esrc[e],     s1 = g_esrc[e + 1];
        int s2 = g_esrc[e + 2], s3 = g_esrc[e + 3];
        float4 v0 = h4_from_u2(h2[s0 * 32 + lane]);
        float4 v1 = h4_from_u2(h2[s1 * 32 + lane]);
        float4 v2 = h4_from_u2(h2[s2 * 32 + lane]);
        float4 v3 = h4_from_u2(h2[s3 * 32 + lane]);
        acc.x += v0.x + v1.x + v2.x + v3.x;
        acc.y += v0.y + v1.y + v2.y + v3.y;
        acc.z += v0.z + v1.z + v2.z + v3.z;
        acc.w += v0.w + v1.w + v2.w + v3.w;
    }
    for (; e < end; e++) {
        float4 v = h4_from_u2(h2[g_esrc[e] * 32 + lane]);
        acc.x += v.x; acc.y += v.y; acc.z += v.z; acc.w += v.w;
    }

    float4 hs = h4_from_u2(h2[node * 32 + lane]);
    float dv = g_dinv[node];
    float4 bb = ((const float4*)bias)[lane];
    float4 o;
    o.x = tanhf(dv * (acc.x + hs.x) + bb.x);
    o.y = tanhf(dv * (acc.y + hs.y) + bb.y);
    o.z = tanhf(dv * (acc.z + hs.z) + bb.z);
    o.w = tanhf(dv * (acc.w + hs.w) + bb.w);

    if (last) {
        ((float4*)g_xB)[node * 32 + lane] = o;
    } else {
        __half2 a = __floats2half2_rn(o.x, o.y);
        __half2 b = __floats2half2_rn(o.z, o.w);
        ((uint2*)g_ax)[node * 32 + lane] = make_uint2(*(uint32_t*)&a, *(uint32_t*)&b);
    }
}

// ---------------- pooling ----------------
__global__ void k_pool_init() {
    int i = blockIdx.x * blockDim.x + threadIdx.x;
    if (i < NG * HF) {
        g_gmax[i] = -INFINITY;
        g_gsum[i] = 0.0f;
    }
    if (i < NG) g_gcnt[i] = 0;
}

__device__ __forceinline__ void atomicMaxF(float* addr, float v) {
    if (v >= 0.0f) atomicMax((int*)addr, __float_as_int(v));
    else           atomicMin((unsigned int*)addr, __float_as_uint(v));
}

__global__ __launch_bounds__(128) void k_pool(const int* __restrict__ batch) {
    const float* __restrict__ x = g_xB;
    int t  = threadIdx.x;
    int n0 = blockIdx.x * POOL_CH;
    if (n0 >= NN) return;
    int n1 = min(n0 + POOL_CH, NN);

    int cur = -1;
    float rmax = -INFINITY, rsum = 0.0f;
    int rcnt = 0;
    for (int n = n0; n < n1; n++) {
        int g = batch[n];
        if (g != cur) {
            if (cur >= 0) {
                atomicMaxF(&g_gmax[cur * HF + t], rmax);
                atomicAdd(&g_gsum[cur * HF + t], rsum);
                if (t == 0) atomicAdd(&g_gcnt[cur], rcnt);
            }
            cur = g; rmax = -INFINITY; rsum = 0.0f; rcnt = 0;
        }
        float v = x[n * HF + t];
        rmax = fmaxf(rmax, v);
        rsum += v;
        rcnt++;
    }
    if (cur >= 0) {
        atomicMaxF(&g_gmax[cur * HF + t], rmax);
        atomicAdd(&g_gsum[cur * HF + t], rsum);
        if (t == 0) atomicAdd(&g_gcnt[cur], rcnt);
    }
}

// ---------------- finalize ----------------
__global__ __launch_bounds__(256) void k_finalize(const float* __restrict__ Wout,
                                                  const float* __restrict__ bout,
                                                  float* __restrict__ dout, int out_size) {
    __shared__ float p[2 * HF];
    int g = blockIdx.x;
    int t = threadIdx.x;

    float val;
    if (t < HF) {
        val = g_gmax[g * HF + t];
    } else {
        float c = fmaxf((float)g_gcnt[g], 1.0f);
        val = g_gsum[g * HF + (t - HF)] / c;
    }
    p[t] = val;
    int pidx = NG * NC + g * (2 * HF) + t;
    if (pidx < out_size) dout[pidx] = val;
    __syncthreads();

    if (t < NC) {
        float s = bout[t];
#pragma unroll 8
        for (int j = 0; j < 2 * HF; j++) s += p[j] * Wout[j * NC + t];
        int oidx = g * NC + t;
        if (oidx < out_size) dout[oidx] = s;
    }
}

// ---------------- launch ----------------
extern "C" void kernel_launch(void* const* d_in, const int* in_sizes, int n_in,
                              void* d_out, int out_size) {
    const float* x     = (const float*)d_in[0];
    const int*   ei    = (const int*)  d_in[1];
    const int*   batch = (const int*)  d_in[2];
    const float* W0 = (const float*)d_in[3];  const float* b0 = (const float*)d_in[4];
    const float* W1 = (const float*)d_in[5];  const float* b1 = (const float*)d_in[6];
    const float* W2 = (const float*)d_in[7];  const float* b2 = (const float*)d_in[8];
    const float* W3 = (const float*)d_in[9];  const float* b3 = (const float*)d_in[10];
    const float* Wout = (const float*)d_in[11];
    const float* bout = (const float*)d_in[12];
    float* dout = (float*)d_out;

    const int* src = ei;
    const int* dst = ei + NE;

    const int TB = 256;
    const int gN  = (NN + TB - 1) / TB;
    const int gE4 = (NE / 4 + TB - 1) / TB;      // 4 edges/thread
    const int gGemm = (NN + 127) / 128;          // 782
    const int gAgg  = (NN + 15) / 16;            // 512-thread blocks, 16 nodes each
    const int gPool = (NN + POOL_CH - 1) / POOL_CH;

    // Idempotent, capture-safe (not a stream op).
    cudaFuncSetAttribute(k_hgemm, cudaFuncAttributeMaxDynamicSharedMemorySize, SMB);

    // ---- graph preprocessing ----
    k_deg_init<<<gN, TB>>>();
    k_deg_count<<<gE4, TB>>>(dst);
    k_scan1<<<NB_SCAN, SCAN_B>>>();              // also computes dinv
    k_scan3<<<gN, TB>>>();                       // scans bsums in-block (scan2 merged)
    k_edge_scatter<<<gE4, TB>>>(src, dst);

    // ---- precision prep ----
    k_split_x<<<(NN * HF / 4 + TB - 1) / TB, TB>>>(x);
    k_wsplit<<<(4 * HF * HF + TB - 1) / TB, TB>>>(W0, W1, W2, W3);

    // ---- 4 GCN layers ----
    const float* biases[4] = {b0, b1, b2, b3};
    for (int l = 0; l < 4; l++) {
        k_hgemm<<<gGemm, 256, SMB>>>(l);
        k_agg<<<gAgg, 512>>>(biases[l], l == 3 ? 1 : 0);
    }

    // ---- pooling + head ----
    k_pool_init<<<(NG * HF + TB - 1) / TB, TB>>>();
    k_pool<<<gPool, 128>>>(batch);
    k_finalize<<<NG, 256>>>(Wout, bout, dout, out_size);
}